// round 1
// baseline (speedup 1.0000x reference)
#include <cuda_runtime.h>
#include <cuda_fp16.h>

#define NA 50000
#define NB 50000
#define DD 64
#define FEAT 16
#define EE 30000

// ---------------- scratch (static device globals; no allocs) ----------------
__device__ float g_xa0[NA * DD];
__device__ float g_xb0[NB * DD];
__device__ float g_xa1[NA * DD];
__device__ float g_xb1[NB * DD];
__device__ float g_hab[EE * DD];
__device__ float g_hba[EE * DD];
__device__ __half g_wab[(size_t)EE * 4096];   // Wm for a->b edges (fp16)
__device__ __half g_wba[(size_t)EE * 4096];   // Wm for b->a edges (fp16)
__device__ float g_ssa[NA * DD];
__device__ float g_ssb[NB * DD];
__device__ float g_cnta[NA];
__device__ float g_cntb[NB];

// ---------------- utility ----------------
__global__ void k_zero(float* __restrict__ p, int n) {
    int i = blockIdx.x * 256 + threadIdx.x;
    if (i < n) p[i] = 0.f;
}

__global__ void k_count(const int* __restrict__ dst, float* __restrict__ cnt, int n) {
    int e = blockIdx.x * 256 + threadIdx.x;
    if (e < n) atomicAdd(&cnt[dst[e]], 1.f);
}

// y[n,:] = emb[idx[n],:] @ W(64x64) + b
__global__ void __launch_bounds__(256) k_node_linear(
    const float* __restrict__ X, const int* __restrict__ idx,
    const float* __restrict__ W, const float* __restrict__ b,
    float* __restrict__ Y, int N)
{
    __shared__ float sW[64 * 64];
    __shared__ float sB[64];
    __shared__ float sX[64][65];
    int tid = threadIdx.x;
    for (int i = tid; i < 4096; i += 256) sW[i] = W[i];
    if (tid < 64) sB[tid] = b[tid];
    int n0 = blockIdx.x * 64;
    int r = tid >> 2, c0 = (tid & 3) * 16;
    int n = n0 + r;
    if (n < N) {
        int s = idx ? idx[n] : n;
        const float4* xr = (const float4*)(X + (size_t)s * 64 + c0);
#pragma unroll
        for (int k = 0; k < 4; k++) {
            float4 v = xr[k];
            sX[r][c0 + 4 * k + 0] = v.x; sX[r][c0 + 4 * k + 1] = v.y;
            sX[r][c0 + 4 * k + 2] = v.z; sX[r][c0 + 4 * k + 3] = v.w;
        }
    } else {
#pragma unroll
        for (int k = 0; k < 16; k++) sX[r][c0 + k] = 0.f;
    }
    __syncthreads();
    int o0 = (tid & 3) * 16;
    float acc[16];
#pragma unroll
    for (int j = 0; j < 16; j++) acc[j] = sB[o0 + j];
#pragma unroll 8
    for (int d = 0; d < 64; d++) {
        float xv = sX[r][d];
#pragma unroll
        for (int j = 0; j < 16; j++) acc[j] += xv * sW[d * 64 + o0 + j];
    }
    if (n < N) {
#pragma unroll
        for (int j = 0; j < 16; j++) Y[(size_t)n * 64 + o0 + j] = acc[j];
    }
}

// H[e,:] = relu(EA[e,:16] @ W1(16x64) + b1)
__global__ void __launch_bounds__(256) k_edge_mlp(
    const float* __restrict__ EA, const float* __restrict__ W1,
    const float* __restrict__ b1, float* __restrict__ H, int Ecnt)
{
    __shared__ float sW[16 * 64];
    __shared__ float sB[64];
    __shared__ float sX[64][17];
    int tid = threadIdx.x;
    for (int i = tid; i < 1024; i += 256) sW[i] = W1[i];
    if (tid < 64) sB[tid] = b1[tid];
    int e0 = blockIdx.x * 64;
    int r = tid >> 2, c0 = (tid & 3) * 4;
    int e = e0 + r;
    if (e < Ecnt) {
        float4 v = *(const float4*)(EA + (size_t)e * 16 + c0);
        sX[r][c0] = v.x; sX[r][c0 + 1] = v.y; sX[r][c0 + 2] = v.z; sX[r][c0 + 3] = v.w;
    } else {
        sX[r][c0] = sX[r][c0 + 1] = sX[r][c0 + 2] = sX[r][c0 + 3] = 0.f;
    }
    __syncthreads();
    int o0 = (tid & 3) * 16;
    float acc[16];
#pragma unroll
    for (int j = 0; j < 16; j++) acc[j] = sB[o0 + j];
#pragma unroll
    for (int d = 0; d < 16; d++) {
        float xv = sX[r][d];
#pragma unroll
        for (int j = 0; j < 16; j++) acc[j] += xv * sW[d * 64 + o0 + j];
    }
    if (e < Ecnt) {
#pragma unroll
        for (int j = 0; j < 16; j++) H[(size_t)e * 64 + o0 + j] = fmaxf(acc[j], 0.f);
    }
}

// C[e, n0:n0+128] = A[e,:64] @ B(64x4096)[:, n0:n0+128] + b2, stored as fp16
__global__ void __launch_bounds__(256) k_gemm1(
    const float* __restrict__ A, const float* __restrict__ B,
    const float* __restrict__ b2, __half* __restrict__ C, int Ecnt)
{
    __shared__ float sAT[64][72];     // [d][row], transposed A tile
    __shared__ float4 sB4[64 * 32];   // [d][col/4] B tile (64 x 128 floats)
    int tid = threadIdx.x;
    int e0 = blockIdx.x * 64;
    int n0 = blockIdx.y * 128;
    {   // load A tile (transposed into smem)
        int r = tid >> 2, c0 = (tid & 3) * 16;
        int e = e0 + r;
        if (e < Ecnt) {
            const float4* ar = (const float4*)(A + (size_t)e * 64 + c0);
#pragma unroll
            for (int k = 0; k < 4; k++) {
                float4 v = ar[k];
                sAT[c0 + 4 * k + 0][r] = v.x; sAT[c0 + 4 * k + 1][r] = v.y;
                sAT[c0 + 4 * k + 2][r] = v.z; sAT[c0 + 4 * k + 3][r] = v.w;
            }
        } else {
#pragma unroll
            for (int k = 0; k < 16; k++) sAT[c0 + k][r] = 0.f;
        }
    }
    {   // load B tile
        for (int i = tid; i < 64 * 32; i += 256) {
            int d = i >> 5, c = i & 31;
            sB4[i] = ((const float4*)(B + (size_t)d * 4096 + n0))[c];
        }
    }
    __syncthreads();
    int r0 = (tid >> 5) * 8;      // 8 rows per thread (uniform within warp)
    int cc = (tid & 31);          // 4 cols per thread
    float acc[8][4] = {};
#pragma unroll 8
    for (int d = 0; d < 64; d++) {
        float4 bv = sB4[d * 32 + cc];
        float4 aA = *(const float4*)&sAT[d][r0];
        float4 aB = *(const float4*)&sAT[d][r0 + 4];
        float av[8] = {aA.x, aA.y, aA.z, aA.w, aB.x, aB.y, aB.z, aB.w};
#pragma unroll
        for (int i = 0; i < 8; i++) {
            acc[i][0] += av[i] * bv.x; acc[i][1] += av[i] * bv.y;
            acc[i][2] += av[i] * bv.z; acc[i][3] += av[i] * bv.w;
        }
    }
    float4 bias4 = ((const float4*)(b2 + n0))[cc];
#pragma unroll
    for (int i = 0; i < 8; i++) {
        int e = e0 + r0 + i;
        if (e < Ecnt) {
            __half2 p0 = __floats2half2_rn(acc[i][0] + bias4.x, acc[i][1] + bias4.y);
            __half2 p1 = __floats2half2_rn(acc[i][2] + bias4.z, acc[i][3] + bias4.w);
            __half2* cp = (__half2*)(C + (size_t)e * 4096 + n0 + cc * 4);
            cp[0] = p0; cp[1] = p1;
        }
    }
}

// per-edge matvec msg = x[src] @ Wm[e], scattered (atomic) into ssum[dst]
__global__ void __launch_bounds__(256) k_matvec(
    const float* __restrict__ X, const __half2* __restrict__ WM,
    const int* __restrict__ SRC, const int* __restrict__ DST,
    float* __restrict__ SS, int Ecnt)
{
    int gw = (blockIdx.x * 256 + threadIdx.x) >> 5;
    int lane = threadIdx.x & 31;
    if (gw >= Ecnt) return;
    int s = SRC[gw];
    const float* xr = X + (size_t)s * 64;
    float x0 = xr[lane], x1 = xr[lane + 32];
    const __half2* w = WM + (size_t)gw * 2048;
    float a0 = 0.f, a1 = 0.f;
#pragma unroll
    for (int d = 0; d < 32; d++) {
        float xd = __shfl_sync(0xffffffffu, x0, d);
        float2 f = __half22float2(w[d * 32 + lane]);
        a0 += xd * f.x; a1 += xd * f.y;
    }
#pragma unroll
    for (int d = 0; d < 32; d++) {
        float xd = __shfl_sync(0xffffffffu, x1, d);
        float2 f = __half22float2(w[(d + 32) * 32 + lane]);
        a0 += xd * f.x; a1 += xd * f.y;
    }
    float* sp = SS + (size_t)DST[gw] * 64 + 2 * lane;
    atomicAdd(sp, a0);
    atomicAdd(sp + 1, a1);
}

// Y[n,:] = relu( SS[n,:]/max(cnt,1) + Xprev[n,:] @ root + bias )
__global__ void __launch_bounds__(256) k_finalize(
    const float* __restrict__ Xprev, const float* __restrict__ SS,
    const float* __restrict__ CNT, const float* __restrict__ W,
    const float* __restrict__ b, float* __restrict__ Y, int N)
{
    __shared__ float sW[64 * 64];
    __shared__ float sB[64];
    __shared__ float sX[64][65];
    int tid = threadIdx.x;
    for (int i = tid; i < 4096; i += 256) sW[i] = W[i];
    if (tid < 64) sB[tid] = b[tid];
    int n0 = blockIdx.x * 64;
    int r = tid >> 2, c0 = (tid & 3) * 16;
    int n = n0 + r;
    if (n < N) {
        const float4* xr = (const float4*)(Xprev + (size_t)n * 64 + c0);
#pragma unroll
        for (int k = 0; k < 4; k++) {
            float4 v = xr[k];
            sX[r][c0 + 4 * k + 0] = v.x; sX[r][c0 + 4 * k + 1] = v.y;
            sX[r][c0 + 4 * k + 2] = v.z; sX[r][c0 + 4 * k + 3] = v.w;
        }
    } else {
#pragma unroll
        for (int k = 0; k < 16; k++) sX[r][c0 + k] = 0.f;
    }
    __syncthreads();
    int o0 = (tid & 3) * 16;
    float acc[16];
#pragma unroll
    for (int j = 0; j < 16; j++) acc[j] = sB[o0 + j];
#pragma unroll 8
    for (int d = 0; d < 64; d++) {
        float xv = sX[r][d];
#pragma unroll
        for (int j = 0; j < 16; j++) acc[j] += xv * sW[d * 64 + o0 + j];
    }
    if (n < N) {
        float ic = 1.f / fmaxf(CNT[n], 1.f);
#pragma unroll
        for (int j = 0; j < 16; j++) {
            float v = acc[j] + SS[(size_t)n * 64 + o0 + j] * ic;
            Y[(size_t)n * 64 + o0 + j] = fmaxf(v, 0.f);
        }
    }
}

// ---------------- launcher ----------------
static void* sym(const void* s) {
    void* p = nullptr;
    cudaGetSymbolAddress(&p, s);
    return p;
}

extern "C" void kernel_launch(void* const* d_in, const int* in_sizes, int n_in,
                              void* d_out, int out_size)
{
    const int*   x_a      = (const int*)d_in[0];
    const int*   x_b      = (const int*)d_in[1];
    const int*   ei_ab    = (const int*)d_in[2];   // [2,E]
    const int*   ei_ba    = (const int*)d_in[3];
    const float* ea_ab    = (const float*)d_in[4];
    const float* ea_ba    = (const float*)d_in[5];
    const float* emb_a    = (const float*)d_in[6];
    const float* emb_b    = (const float*)d_in[7];
    const float* Wn_a     = (const float*)d_in[8];
    const float* bn_a     = (const float*)d_in[9];
    const float* Wn_b     = (const float*)d_in[10];
    const float* bn_b     = (const float*)d_in[11];
    const float* W1_ab    = (const float*)d_in[12];
    const float* b1_ab    = (const float*)d_in[13];
    const float* W2_ab    = (const float*)d_in[14];
    const float* b2_ab    = (const float*)d_in[15];
    const float* W1_ba    = (const float*)d_in[16];
    const float* b1_ba    = (const float*)d_in[17];
    const float* W2_ba    = (const float*)d_in[18];
    const float* b2_ba    = (const float*)d_in[19];
    const float* root0_ab = (const float*)d_in[20];
    const float* bias0_ab = (const float*)d_in[21];
    const float* root0_ba = (const float*)d_in[22];
    const float* bias0_ba = (const float*)d_in[23];
    const float* root1_ab = (const float*)d_in[24];
    const float* bias1_ab = (const float*)d_in[25];
    const float* root1_ba = (const float*)d_in[26];
    const float* bias1_ba = (const float*)d_in[27];

    float* xa0 = (float*)sym(g_xa0);
    float* xb0 = (float*)sym(g_xb0);
    float* xa1 = (float*)sym(g_xa1);
    float* xb1 = (float*)sym(g_xb1);
    float* hab = (float*)sym(g_hab);
    float* hba = (float*)sym(g_hba);
    __half* wab = (__half*)sym(g_wab);
    __half* wba = (__half*)sym(g_wba);
    float* ssa = (float*)sym(g_ssa);
    float* ssb = (float*)sym(g_ssb);
    float* cnta = (float*)sym(g_cnta);
    float* cntb = (float*)sym(g_cntb);

    const int* src_ab = ei_ab;
    const int* dst_ab = ei_ab + EE;
    const int* src_ba = ei_ba;
    const int* dst_ba = ei_ba + EE;

    float* out = (float*)d_out;

    const int NBLK_NODE = (NA + 63) / 64;        // 782
    const int NBLK_EDGE = (EE + 63) / 64;        // 469
    const int NBLK_MV   = (EE * 32 + 255) / 256; // 3750

    // counts (layer-invariant)
    k_zero<<<(NA + 255) / 256, 256>>>(cnta, NA);
    k_zero<<<(NB + 255) / 256, 256>>>(cntb, NB);
    k_count<<<(EE + 255) / 256, 256>>>(dst_ab, cntb, EE);
    k_count<<<(EE + 255) / 256, 256>>>(dst_ba, cnta, EE);

    // initial node features
    k_node_linear<<<NBLK_NODE, 256>>>(emb_a, x_a, Wn_a, bn_a, xa0, NA);
    k_node_linear<<<NBLK_NODE, 256>>>(emb_b, x_b, Wn_b, bn_b, xb0, NB);

    // edge MLP hidden (layer-invariant)
    k_edge_mlp<<<NBLK_EDGE, 256>>>(ea_ab, W1_ab, b1_ab, hab, EE);
    k_edge_mlp<<<NBLK_EDGE, 256>>>(ea_ba, W1_ba, b1_ba, hba, EE);

    // per-edge weight matrices Wm (layer-invariant, fp16)
    dim3 g1(NBLK_EDGE, 32);
    k_gemm1<<<g1, 256>>>(hab, W2_ab, b2_ab, wab, EE);
    k_gemm1<<<g1, 256>>>(hba, W2_ba, b2_ba, wba, EE);

    // ---- layer 0 ----
    k_zero<<<(NB * DD + 255) / 256, 256>>>(ssb, NB * DD);
    k_zero<<<(NA * DD + 255) / 256, 256>>>(ssa, NA * DD);
    k_matvec<<<NBLK_MV, 256>>>(xa0, (const __half2*)wab, src_ab, dst_ab, ssb, EE);
    k_matvec<<<NBLK_MV, 256>>>(xb0, (const __half2*)wba, src_ba, dst_ba, ssa, EE);
    k_finalize<<<NBLK_NODE, 256>>>(xb0, ssb, cntb, root0_ab, bias0_ab, xb1, NB);
    k_finalize<<<NBLK_NODE, 256>>>(xa0, ssa, cnta, root0_ba, bias0_ba, xa1, NA);

    // ---- layer 1 ----
    k_zero<<<(NB * DD + 255) / 256, 256>>>(ssb, NB * DD);
    k_zero<<<(NA * DD + 255) / 256, 256>>>(ssa, NA * DD);
    k_matvec<<<NBLK_MV, 256>>>(xa1, (const __half2*)wab, src_ab, dst_ab, ssb, EE);
    k_matvec<<<NBLK_MV, 256>>>(xb1, (const __half2*)wba, src_ba, dst_ba, ssa, EE);
    k_finalize<<<NBLK_NODE, 256>>>(xb1, ssb, cntb, root1_ab, bias1_ab, out + (size_t)NA * DD, NB);
    k_finalize<<<NBLK_NODE, 256>>>(xa1, ssa, cnta, root1_ba, bias1_ba, out, NA);
}

// round 3
// speedup vs baseline: 1.4913x; 1.4913x over previous
#include <cuda_runtime.h>
#include <cuda_fp16.h>
#include <cstdint>

#define NA 50000
#define NB 50000
#define DD 64
#define FEAT 16
#define EE 30000
#define EPAD 30080   // 235 * 128, padded M for 128-row MMA tiles

// ---------------- scratch (static device globals; no allocs) ----------------
__device__ float  g_xa0[NA * DD];
__device__ float  g_xb0[NB * DD];
__device__ float  g_xa1[NA * DD];
__device__ float  g_xb1[NB * DD];
__device__ __half g_hab[EPAD * DD];               // edge-MLP hidden, fp16 (zero-padded rows)
__device__ __half g_hba[EPAD * DD];
__device__ __half g_w2t_ab[4096 * 64];            // W2^T fp16 [N=4096, K=64]
__device__ __half g_w2t_ba[4096 * 64];
__device__ __half g_wab[(size_t)EE * 4096];       // per-edge weight matrices (fp16)
__device__ __half g_wba[(size_t)EE * 4096];
__device__ float  g_ssa[NA * DD];
__device__ float  g_ssb[NB * DD];
__device__ float  g_cnta[NA];
__device__ float  g_cntb[NB];

// ---------------- helpers ----------------
__device__ __forceinline__ uint32_t smem_u32(const void* p) {
    uint32_t a;
    asm("{ .reg .u64 t; cvta.to.shared.u64 t, %1; cvt.u32.u64 %0, t; }" : "=r"(a) : "l"(p));
    return a;
}

__device__ __forceinline__ void ldsm_x4(uint32_t& r0, uint32_t& r1, uint32_t& r2, uint32_t& r3,
                                        uint32_t addr) {
    asm volatile("ldmatrix.sync.aligned.m8n8.x4.shared.b16 {%0,%1,%2,%3}, [%4];"
                 : "=r"(r0), "=r"(r1), "=r"(r2), "=r"(r3) : "r"(addr));
}

__device__ __forceinline__ void mma16816(float* d, const uint32_t* a, const uint32_t* b) {
    asm volatile(
        "mma.sync.aligned.m16n8k16.row.col.f32.f16.f16.f32 "
        "{%0,%1,%2,%3}, {%4,%5,%6,%7}, {%8,%9}, {%0,%1,%2,%3};"
        : "+f"(d[0]), "+f"(d[1]), "+f"(d[2]), "+f"(d[3])
        : "r"(a[0]), "r"(a[1]), "r"(a[2]), "r"(a[3]), "r"(b[0]), "r"(b[1]));
}

// ---------------- utility kernels ----------------
__global__ void k_zero(float* __restrict__ p, int n) {
    int i = blockIdx.x * 256 + threadIdx.x;
    if (i < n) p[i] = 0.f;
}

__global__ void k_count(const int* __restrict__ dst, float* __restrict__ cnt, int n) {
    int e = blockIdx.x * 256 + threadIdx.x;
    if (e < n) atomicAdd(&cnt[dst[e]], 1.f);
}

// W2 [64, 4096] fp32 -> W2^T [4096, 64] fp16
__global__ void k_transpose_w2(const float* __restrict__ W2, __half* __restrict__ BT) {
    int i = blockIdx.x * 256 + threadIdx.x;   // i = n*64 + k
    if (i < 4096 * 64) {
        int n = i >> 6, k = i & 63;
        BT[i] = __float2half(W2[k * 4096 + n]);
    }
}

// y[n,:] = emb[idx[n],:] @ W(64x64) + b
__global__ void __launch_bounds__(256) k_node_linear(
    const float* __restrict__ X, const int* __restrict__ idx,
    const float* __restrict__ W, const float* __restrict__ b,
    float* __restrict__ Y, int N)
{
    __shared__ float sW[64 * 64];
    __shared__ float sB[64];
    __shared__ float sX[64][65];
    int tid = threadIdx.x;
    for (int i = tid; i < 4096; i += 256) sW[i] = W[i];
    if (tid < 64) sB[tid] = b[tid];
    int n0 = blockIdx.x * 64;
    int r = tid >> 2, c0 = (tid & 3) * 16;
    int n = n0 + r;
    if (n < N) {
        int s = idx ? idx[n] : n;
        const float4* xr = (const float4*)(X + (size_t)s * 64 + c0);
#pragma unroll
        for (int k = 0; k < 4; k++) {
            float4 v = xr[k];
            sX[r][c0 + 4 * k + 0] = v.x; sX[r][c0 + 4 * k + 1] = v.y;
            sX[r][c0 + 4 * k + 2] = v.z; sX[r][c0 + 4 * k + 3] = v.w;
        }
    } else {
#pragma unroll
        for (int k = 0; k < 16; k++) sX[r][c0 + k] = 0.f;
    }
    __syncthreads();
    int o0 = (tid & 3) * 16;
    float acc[16];
#pragma unroll
    for (int j = 0; j < 16; j++) acc[j] = sB[o0 + j];
#pragma unroll 8
    for (int d = 0; d < 64; d++) {
        float xv = sX[r][d];
#pragma unroll
        for (int j = 0; j < 16; j++) acc[j] += xv * sW[d * 64 + o0 + j];
    }
    if (n < N) {
#pragma unroll
        for (int j = 0; j < 16; j++) Y[(size_t)n * 64 + o0 + j] = acc[j];
    }
}

// H[e,:] = relu(EA[e,:16] @ W1(16x64) + b1), stored fp16; rows [EE,EPAD) zeroed
__global__ void __launch_bounds__(256) k_edge_mlp(
    const float* __restrict__ EA, const float* __restrict__ W1,
    const float* __restrict__ b1, __half* __restrict__ H, int Ecnt)
{
    __shared__ float sW[16 * 64];
    __shared__ float sB[64];
    __shared__ float sX[64][17];
    int tid = threadIdx.x;
    for (int i = tid; i < 1024; i += 256) sW[i] = W1[i];
    if (tid < 64) sB[tid] = b1[tid];
    int e0 = blockIdx.x * 64;
    int r = tid >> 2, c0 = (tid & 3) * 4;
    int e = e0 + r;
    if (e < Ecnt) {
        float4 v = *(const float4*)(EA + (size_t)e * 16 + c0);
        sX[r][c0] = v.x; sX[r][c0 + 1] = v.y; sX[r][c0 + 2] = v.z; sX[r][c0 + 3] = v.w;
    } else {
        sX[r][c0] = sX[r][c0 + 1] = sX[r][c0 + 2] = sX[r][c0 + 3] = 0.f;
    }
    __syncthreads();
    int o0 = (tid & 3) * 16;
    float acc[16];
#pragma unroll
    for (int j = 0; j < 16; j++) acc[j] = sB[o0 + j];
#pragma unroll
    for (int d = 0; d < 16; d++) {
        float xv = sX[r][d];
#pragma unroll
        for (int j = 0; j < 16; j++) acc[j] += xv * sW[d * 64 + o0 + j];
    }
    if (e < Ecnt) {
#pragma unroll
        for (int j = 0; j < 16; j++) H[(size_t)e * 64 + o0 + j] = __float2half(fmaxf(acc[j], 0.f));
    } else {
#pragma unroll
        for (int j = 0; j < 16; j++) H[(size_t)e * 64 + o0 + j] = __float2half(0.f);
    }
}

// ---------------- HMMA GEMM1: C[e,:4096] = A[e,:64] @ W2 + b2 (fp16 out) -----
// CTA tile: 128(M) x 128(N), K=64. 8 warps = 4(M) x 2(N); warptile 32x64.
// blockIdx.x = M-tile (235), blockIdx.y = N-group (4); each CTA loops 8 N-tiles.
__global__ void __launch_bounds__(256) k_gemm1_mma(
    const __half* __restrict__ A, const __half* __restrict__ BT,
    const float* __restrict__ b2, __half* __restrict__ C, int Ecnt)
{
    __shared__ __half sA[128][72];
    __shared__ __half sB[128][72];
    const int tid = threadIdx.x, lane = tid & 31, wid = tid >> 5;
    const int e0 = blockIdx.x * 128;
    const int warpM = (wid & 3) * 32;
    const int warpN = (wid >> 2) * 64;

    // stage A tile (rows are zero-padded in g_h* up to EPAD)
    {
        int row = tid >> 1;
        const uint4* ar = (const uint4*)(A + (size_t)(e0 + row) * 64) + (tid & 1) * 4;
        uint4* sp = (uint4*)&sA[row][(tid & 1) * 32];
        sp[0] = ar[0]; sp[1] = ar[1]; sp[2] = ar[2]; sp[3] = ar[3];
    }
    __syncthreads();

    // preload A fragments: aF[mt][ks][4] — held across all N-tiles
    uint32_t aF[2][4][4];
#pragma unroll
    for (int mt = 0; mt < 2; mt++) {
#pragma unroll
        for (int ks = 0; ks < 4; ks++) {
            int r = warpM + mt * 16 + (lane & 15);
            int c = ks * 16 + ((lane >> 4) << 3);
            ldsm_x4(aF[mt][ks][0], aF[mt][ks][1], aF[mt][ks][2], aF[mt][ks][3],
                    smem_u32(&sA[r][c]));
        }
    }

    for (int nt = 0; nt < 8; nt++) {
        const int n0 = (blockIdx.y * 8 + nt) * 128;
        __syncthreads();   // sA done (first iter) / prev iter's sB reads done
        {
            int row = tid >> 1;
            const uint4* br = (const uint4*)(BT + (size_t)(n0 + row) * 64) + (tid & 1) * 4;
            uint4* sp = (uint4*)&sB[row][(tid & 1) * 32];
            sp[0] = br[0]; sp[1] = br[1]; sp[2] = br[2]; sp[3] = br[3];
        }
        __syncthreads();

        float acc[2][8][4];
#pragma unroll
        for (int mt = 0; mt < 2; mt++)
#pragma unroll
            for (int j = 0; j < 8; j++)
#pragma unroll
                for (int q = 0; q < 4; q++) acc[mt][j][q] = 0.f;

#pragma unroll
        for (int ks = 0; ks < 4; ks++) {
            uint32_t bF[8][2];
#pragma unroll
            for (int p = 0; p < 4; p++) {   // pairs of n8 tiles
                int r = warpN + p * 16 + (lane & 15);
                int c = ks * 16 + ((lane >> 4) << 3);
                ldsm_x4(bF[2 * p][0], bF[2 * p + 1][0], bF[2 * p][1], bF[2 * p + 1][1],
                        smem_u32(&sB[r][c]));
            }
#pragma unroll
            for (int mt = 0; mt < 2; mt++)
#pragma unroll
                for (int j = 0; j < 8; j++)
                    mma16816(acc[mt][j], aF[mt][ks], bF[j]);
        }

        // epilogue: bias add + fp16 convert + half2 stores
#pragma unroll
        for (int mt = 0; mt < 2; mt++) {
            int r = e0 + warpM + mt * 16 + (lane >> 2);
#pragma unroll
            for (int j = 0; j < 8; j++) {
                int col = n0 + warpN + 8 * j + 2 * (lane & 3);
                float2 bb = *(const float2*)(b2 + col);
                __half2 h01 = __floats2half2_rn(acc[mt][j][0] + bb.x, acc[mt][j][1] + bb.y);
                __half2 h23 = __floats2half2_rn(acc[mt][j][2] + bb.x, acc[mt][j][3] + bb.y);
                if (r < Ecnt)     *(__half2*)(C + (size_t)r * 4096 + col) = h01;
                if (r + 8 < Ecnt) *(__half2*)(C + (size_t)(r + 8) * 4096 + col) = h23;
            }
        }
    }
}

// per-edge matvec msg = x[src] @ Wm[e], scattered (atomic) into ssum[dst]
__global__ void __launch_bounds__(256) k_matvec(
    const float* __restrict__ X, const __half2* __restrict__ WM,
    const int* __restrict__ SRC, const int* __restrict__ DST,
    float* __restrict__ SS, int Ecnt)
{
    int gw = (blockIdx.x * 256 + threadIdx.x) >> 5;
    int lane = threadIdx.x & 31;
    if (gw >= Ecnt) return;
    int s = SRC[gw];
    const float* xr = X + (size_t)s * 64;
    float x0 = xr[lane], x1 = xr[lane + 32];
    const __half2* w = WM + (size_t)gw * 2048;
    float a0 = 0.f, a1 = 0.f;
#pragma unroll
    for (int d = 0; d < 32; d++) {
        float xd = __shfl_sync(0xffffffffu, x0, d);
        float2 f = __half22float2(w[d * 32 + lane]);
        a0 += xd * f.x; a1 += xd * f.y;
    }
#pragma unroll
    for (int d = 0; d < 32; d++) {
        float xd = __shfl_sync(0xffffffffu, x1, d);
        float2 f = __half22float2(w[(d + 32) * 32 + lane]);
        a0 += xd * f.x; a1 += xd * f.y;
    }
    float* sp = SS + (size_t)DST[gw] * 64 + 2 * lane;
    atomicAdd(sp, a0);
    atomicAdd(sp + 1, a1);
}

// Y[n,:] = relu( SS[n,:]/max(cnt,1) + Xprev[n,:] @ root + bias )
__global__ void __launch_bounds__(256) k_finalize(
    const float* __restrict__ Xprev, const float* __restrict__ SS,
    const float* __restrict__ CNT, const float* __restrict__ W,
    const float* __restrict__ b, float* __restrict__ Y, int N)
{
    __shared__ float sW[64 * 64];
    __shared__ float sB[64];
    __shared__ float sX[64][65];
    int tid = threadIdx.x;
    for (int i = tid; i < 4096; i += 256) sW[i] = W[i];
    if (tid < 64) sB[tid] = b[tid];
    int n0 = blockIdx.x * 64;
    int r = tid >> 2, c0 = (tid & 3) * 16;
    int n = n0 + r;
    if (n < N) {
        const float4* xr = (const float4*)(Xprev + (size_t)n * 64 + c0);
#pragma unroll
        for (int k = 0; k < 4; k++) {
            float4 v = xr[k];
            sX[r][c0 + 4 * k + 0] = v.x; sX[r][c0 + 4 * k + 1] = v.y;
            sX[r][c0 + 4 * k + 2] = v.z; sX[r][c0 + 4 * k + 3] = v.w;
        }
    } else {
#pragma unroll
        for (int k = 0; k < 16; k++) sX[r][c0 + k] = 0.f;
    }
    __syncthreads();
    int o0 = (tid & 3) * 16;
    float acc[16];
#pragma unroll
    for (int j = 0; j < 16; j++) acc[j] = sB[o0 + j];
#pragma unroll 8
    for (int d = 0; d < 64; d++) {
        float xv = sX[r][d];
#pragma unroll
        for (int j = 0; j < 16; j++) acc[j] += xv * sW[d * 64 + o0 + j];
    }
    if (n < N) {
        float ic = 1.f / fmaxf(CNT[n], 1.f);
#pragma unroll
        for (int j = 0; j < 16; j++) {
            float v = acc[j] + SS[(size_t)n * 64 + o0 + j] * ic;
            Y[(size_t)n * 64 + o0 + j] = fmaxf(v, 0.f);
        }
    }
}

// ---------------- launcher ----------------
static void* sym(const void* s) {
    void* p = nullptr;
    cudaGetSymbolAddress(&p, s);
    return p;
}

extern "C" void kernel_launch(void* const* d_in, const int* in_sizes, int n_in,
                              void* d_out, int out_size)
{
    const int*   x_a      = (const int*)d_in[0];
    const int*   x_b      = (const int*)d_in[1];
    const int*   ei_ab    = (const int*)d_in[2];   // [2,E]
    const int*   ei_ba    = (const int*)d_in[3];
    const float* ea_ab    = (const float*)d_in[4];
    const float* ea_ba    = (const float*)d_in[5];
    const float* emb_a    = (const float*)d_in[6];
    const float* emb_b    = (const float*)d_in[7];
    const float* Wn_a     = (const float*)d_in[8];
    const float* bn_a     = (const float*)d_in[9];
    const float* Wn_b     = (const float*)d_in[10];
    const float* bn_b     = (const float*)d_in[11];
    const float* W1_ab    = (const float*)d_in[12];
    const float* b1_ab    = (const float*)d_in[13];
    const float* W2_ab    = (const float*)d_in[14];
    const float* b2_ab    = (const float*)d_in[15];
    const float* W1_ba    = (const float*)d_in[16];
    const float* b1_ba    = (const float*)d_in[17];
    const float* W2_ba    = (const float*)d_in[18];
    const float* b2_ba    = (const float*)d_in[19];
    const float* root0_ab = (const float*)d_in[20];
    const float* bias0_ab = (const float*)d_in[21];
    const float* root0_ba = (const float*)d_in[22];
    const float* bias0_ba = (const float*)d_in[23];
    const float* root1_ab = (const float*)d_in[24];
    const float* bias1_ab = (const float*)d_in[25];
    const float* root1_ba = (const float*)d_in[26];
    const float* bias1_ba = (const float*)d_in[27];

    float*  xa0 = (float*)sym(g_xa0);
    float*  xb0 = (float*)sym(g_xb0);
    float*  xa1 = (float*)sym(g_xa1);
    float*  xb1 = (float*)sym(g_xb1);
    __half* hab = (__half*)sym(g_hab);
    __half* hba = (__half*)sym(g_hba);
    __half* w2tab = (__half*)sym(g_w2t_ab);
    __half* w2tba = (__half*)sym(g_w2t_ba);
    __half* wab = (__half*)sym(g_wab);
    __half* wba = (__half*)sym(g_wba);
    float*  ssa = (float*)sym(g_ssa);
    float*  ssb = (float*)sym(g_ssb);
    float*  cnta = (float*)sym(g_cnta);
    float*  cntb = (float*)sym(g_cntb);

    const int* src_ab = ei_ab;
    const int* dst_ab = ei_ab + EE;
    const int* src_ba = ei_ba;
    const int* dst_ba = ei_ba + EE;

    float* out = (float*)d_out;

    const int NBLK_NODE = (NA + 63) / 64;        // 782
    const int NBLK_EDGEP = EPAD / 64;            // 470 (writes zero padding)
    const int NBLK_MV   = (EE * 32 + 255) / 256; // 3750
    dim3 gmma(EPAD / 128, 4);                    // (235, 4)

    // counts (layer-invariant)
    k_zero<<<(NA + 255) / 256, 256>>>(cnta, NA);
    k_zero<<<(NB + 255) / 256, 256>>>(cntb, NB);
    k_count<<<(EE + 255) / 256, 256>>>(dst_ab, cntb, EE);
    k_count<<<(EE + 255) / 256, 256>>>(dst_ba, cnta, EE);

    // initial node features
    k_node_linear<<<NBLK_NODE, 256>>>(emb_a, x_a, Wn_a, bn_a, xa0, NA);
    k_node_linear<<<NBLK_NODE, 256>>>(emb_b, x_b, Wn_b, bn_b, xb0, NB);

    // edge MLP hidden (layer-invariant, fp16, zero-padded)
    k_edge_mlp<<<NBLK_EDGEP, 256>>>(ea_ab, W1_ab, b1_ab, hab, EE);
    k_edge_mlp<<<NBLK_EDGEP, 256>>>(ea_ba, W1_ba, b1_ba, hba, EE);

    // W2 transposes (layer-invariant)
    k_transpose_w2<<<1024, 256>>>(W2_ab, w2tab);
    k_transpose_w2<<<1024, 256>>>(W2_ba, w2tba);

    // per-edge weight matrices Wm (layer-invariant, fp16) — HMMA tensor cores
    k_gemm1_mma<<<gmma, 256>>>(hab, w2tab, b2_ab, wab, EE);
    k_gemm1_mma<<<gmma, 256>>>(hba, w2tba, b2_ba, wba, EE);

    // ---- layer 0 ----
    k_zero<<<(NB * DD + 255) / 256, 256>>>(ssb, NB * DD);
    k_zero<<<(NA * DD + 255) / 256, 256>>>(ssa, NA * DD);
    k_matvec<<<NBLK_MV, 256>>>(xa0, (const __half2*)wab, src_ab, dst_ab, ssb, EE);
    k_matvec<<<NBLK_MV, 256>>>(xb0, (const __half2*)wba, src_ba, dst_ba, ssa, EE);
    k_finalize<<<NBLK_NODE, 256>>>(xb0, ssb, cntb, root0_ab, bias0_ab, xb1, NB);
    k_finalize<<<NBLK_NODE, 256>>>(xa0, ssa, cnta, root0_ba, bias0_ba, xa1, NA);

    // ---- layer 1 ----
    k_zero<<<(NB * DD + 255) / 256, 256>>>(ssb, NB * DD);
    k_zero<<<(NA * DD + 255) / 256, 256>>>(ssa, NA * DD);
    k_matvec<<<NBLK_MV, 256>>>(xa1, (const __half2*)wab, src_ab, dst_ab, ssb, EE);
    k_matvec<<<NBLK_MV, 256>>>(xb1, (const __half2*)wba, src_ba, dst_ba, ssa, EE);
    k_finalize<<<NBLK_NODE, 256>>>(xb1, ssb, cntb, root1_ab, bias1_ab, out + (size_t)NA * DD, NB);
    k_finalize<<<NBLK_NODE, 256>>>(xa1, ssa, cnta, root1_ba, bias1_ba, out, NA);
}

// round 4
// speedup vs baseline: 2.1861x; 1.4659x over previous
#include <cuda_runtime.h>
#include <cuda_fp16.h>
#include <cstdint>

#define NA 50000
#define NB 50000
#define DD 64
#define FEAT 16
#define EE 30000
#define EPAD 30080     // 235 * 128
#define NBLK_C 235     // conv M-tiles per edge type
#define KW 4160        // packed K: 64*64 + 64 bias rows

// ---------------- scratch (static device globals; no allocs) ----------------
__device__ float  g_xa0[NA * DD];
__device__ float  g_xb0[NB * DD];
__device__ float  g_xa1[NA * DD];
__device__ float  g_xb1[NB * DD];
__device__ __half g_hab[EPAD * DD];      // edge-MLP hidden, fp16, zero-padded rows
__device__ __half g_hba[EPAD * DD];
__device__ __half g_wn_ab[64 * KW];      // packed W2: wn[o][h*64+d] = W2[h][d*64+o]; wn[o][4096+d]=b2[d*64+o]
__device__ __half g_wn_ba[64 * KW];
__device__ float  g_ss[(NA + NB) * DD];  // ssa = g_ss, ssb = g_ss + NA*DD
__device__ float  g_cnt[NA + NB];        // cnta = g_cnt, cntb = g_cnt + NA

// ---------------- helpers ----------------
__device__ __forceinline__ uint32_t smem_u32(const void* p) {
    uint32_t a;
    asm("{ .reg .u64 t; cvta.to.shared.u64 t, %1; cvt.u32.u64 %0, t; }" : "=r"(a) : "l"(p));
    return a;
}

__device__ __forceinline__ void ldsm_x4(uint32_t& r0, uint32_t& r1, uint32_t& r2, uint32_t& r3,
                                        uint32_t addr) {
    asm volatile("ldmatrix.sync.aligned.m8n8.x4.shared.b16 {%0,%1,%2,%3}, [%4];"
                 : "=r"(r0), "=r"(r1), "=r"(r2), "=r"(r3) : "r"(addr));
}

__device__ __forceinline__ void mma16816(float* d, const uint32_t* a, const uint32_t* b) {
    asm volatile(
        "mma.sync.aligned.m16n8k16.row.col.f32.f16.f16.f32 "
        "{%0,%1,%2,%3}, {%4,%5,%6,%7}, {%8,%9}, {%0,%1,%2,%3};"
        : "+f"(d[0]), "+f"(d[1]), "+f"(d[2]), "+f"(d[3])
        : "r"(a[0]), "r"(a[1]), "r"(a[2]), "r"(a[3]), "r"(b[0]), "r"(b[1]));
}

__device__ __forceinline__ uint32_t f2h2(float x, float y) {
    __half2 h = __floats2half2_rn(x, y);
    return *(uint32_t*)&h;
}

__device__ __forceinline__ uint32_t hmul2u(uint32_t a, uint32_t s) {
    __half2 r = __hmul2(*(__half2*)&a, *(__half2*)&s);
    return *(uint32_t*)&r;
}

// ---------------- utility kernels ----------------
__global__ void k_zero(float* __restrict__ p, int n) {
    int i = blockIdx.x * 256 + threadIdx.x;
    if (i < n) p[i] = 0.f;
}

__global__ void k_count2(const int* __restrict__ dst_ab, const int* __restrict__ dst_ba,
                         float* __restrict__ cnta, float* __restrict__ cntb) {
    int i = blockIdx.x * 256 + threadIdx.x;
    if (i < EE) atomicAdd(&cntb[dst_ab[i]], 1.f);
    else if (i < 2 * EE) atomicAdd(&cnta[dst_ba[i - EE]], 1.f);
}

// pack W2 + b2 for both edge types
__global__ void k_pack2(const float* __restrict__ W2a, const float* __restrict__ b2a,
                        __half* __restrict__ WNa,
                        const float* __restrict__ W2b, const float* __restrict__ b2b,
                        __half* __restrict__ WNb) {
    int i = blockIdx.x * 256 + threadIdx.x;   // over 2 * 64 * KW
    const float* W2; const float* b2; __half* WN;
    if (i < 64 * KW) { W2 = W2a; b2 = b2a; WN = WNa; }
    else { i -= 64 * KW; if (i >= 64 * KW) return; W2 = W2b; b2 = b2b; WN = WNb; }
    int o = i / KW, k = i % KW;
    float v;
    if (k < 4096) { int h = k >> 6, d = k & 63; v = W2[h * 4096 + d * 64 + o]; }
    else { int d = k - 4096; v = b2[d * 64 + o]; }
    WN[o * KW + k] = __float2half(v);
}

// y[n,:] = emb[idx[n],:] @ W(64x64) + b   (merged a/b)
__global__ void __launch_bounds__(256) k_node_linear2(
    const float* __restrict__ Xa, const int* __restrict__ ixa,
    const float* __restrict__ Wa, const float* __restrict__ ba, float* __restrict__ Ya,
    const float* __restrict__ Xb, const int* __restrict__ ixb,
    const float* __restrict__ Wb, const float* __restrict__ bb, float* __restrict__ Yb)
{
    __shared__ float sW[64 * 64];
    __shared__ float sB[64];
    __shared__ float sX[64][65];
    int bid = blockIdx.x;
    const float* X; const int* idx; const float* W; const float* b; float* Y; int N;
    if (bid < 782) { X = Xa; idx = ixa; W = Wa; b = ba; Y = Ya; N = NA; }
    else { bid -= 782; X = Xb; idx = ixb; W = Wb; b = bb; Y = Yb; N = NB; }
    int tid = threadIdx.x;
    for (int i = tid; i < 4096; i += 256) sW[i] = W[i];
    if (tid < 64) sB[tid] = b[tid];
    int n0 = bid * 64;
    int r = tid >> 2, c0 = (tid & 3) * 16;
    int n = n0 + r;
    if (n < N) {
        int s = idx[n];
        const float4* xr = (const float4*)(X + (size_t)s * 64 + c0);
#pragma unroll
        for (int k = 0; k < 4; k++) {
            float4 v = xr[k];
            sX[r][c0 + 4 * k + 0] = v.x; sX[r][c0 + 4 * k + 1] = v.y;
            sX[r][c0 + 4 * k + 2] = v.z; sX[r][c0 + 4 * k + 3] = v.w;
        }
    } else {
#pragma unroll
        for (int k = 0; k < 16; k++) sX[r][c0 + k] = 0.f;
    }
    __syncthreads();
    int o0 = (tid & 3) * 16;
    float acc[16];
#pragma unroll
    for (int j = 0; j < 16; j++) acc[j] = sB[o0 + j];
#pragma unroll 8
    for (int d = 0; d < 64; d++) {
        float xv = sX[r][d];
#pragma unroll
        for (int j = 0; j < 16; j++) acc[j] += xv * sW[d * 64 + o0 + j];
    }
    if (n < N) {
#pragma unroll
        for (int j = 0; j < 16; j++) Y[(size_t)n * 64 + o0 + j] = acc[j];
    }
}

// H[e,:] = relu(EA[e,:16] @ W1 + b1) fp16, zero pad rows [EE,EPAD)  (merged)
__global__ void __launch_bounds__(256) k_edge_mlp2(
    const float* __restrict__ EAa, const float* __restrict__ W1a,
    const float* __restrict__ b1a, __half* __restrict__ Ha,
    const float* __restrict__ EAb, const float* __restrict__ W1b,
    const float* __restrict__ b1b, __half* __restrict__ Hb)
{
    __shared__ float sW[16 * 64];
    __shared__ float sB[64];
    __shared__ float sX[64][17];
    int bid = blockIdx.x;
    const float* EA; const float* W1; const float* b1; __half* H;
    if (bid < 470) { EA = EAa; W1 = W1a; b1 = b1a; H = Ha; }
    else { bid -= 470; EA = EAb; W1 = W1b; b1 = b1b; H = Hb; }
    int tid = threadIdx.x;
    for (int i = tid; i < 1024; i += 256) sW[i] = W1[i];
    if (tid < 64) sB[tid] = b1[tid];
    int e0 = bid * 64;
    int r = tid >> 2, c0 = (tid & 3) * 4;
    int e = e0 + r;
    if (e < EE) {
        float4 v = *(const float4*)(EA + (size_t)e * 16 + c0);
        sX[r][c0] = v.x; sX[r][c0 + 1] = v.y; sX[r][c0 + 2] = v.z; sX[r][c0 + 3] = v.w;
    } else {
        sX[r][c0] = sX[r][c0 + 1] = sX[r][c0 + 2] = sX[r][c0 + 3] = 0.f;
    }
    __syncthreads();
    int o0 = (tid & 3) * 16;
    float acc[16];
#pragma unroll
    for (int j = 0; j < 16; j++) acc[j] = sB[o0 + j];
#pragma unroll
    for (int d = 0; d < 16; d++) {
        float xv = sX[r][d];
#pragma unroll
        for (int j = 0; j < 16; j++) acc[j] += xv * sW[d * 64 + o0 + j];
    }
    if (e < EE) {
#pragma unroll
        for (int j = 0; j < 16; j++) H[(size_t)e * 64 + o0 + j] = __float2half(fmaxf(acc[j], 0.f));
    } else {
#pragma unroll
        for (int j = 0; j < 16; j++) H[(size_t)e * 64 + o0 + j] = __float2half(0.f);
    }
}

// ---------------- fused conv: msg[e,:] = (h[e] ⊗ x[src[e]]) @ W2v, atomically
// scattered into SS[dst[e]].  Both edge types in one grid (2*NBLK_C CTAs).
// CTA: 128 edges, 8 warps (16 rows each, all 64 output cols).
__global__ void __launch_bounds__(256) k_conv2(
    const float* __restrict__ Xa, const __half* __restrict__ Ha,
    const __half* __restrict__ WNa, const int* __restrict__ SRCa,
    const int* __restrict__ DSTa, float* __restrict__ SSa,
    const float* __restrict__ Xb, const __half* __restrict__ Hb,
    const __half* __restrict__ WNb, const int* __restrict__ SRCb,
    const int* __restrict__ DSTb, float* __restrict__ SSb)
{
    __shared__ __half sH[128 * 72];      // h tile, padded stride 72
    __shared__ __half sB[2 * 64 * 72];   // double-buffered B tile [64 n][64 k]
    int bid = blockIdx.x;
    const float* X; const __half* H; const __half* WN;
    const int* SRC; const int* DST; float* SS;
    if (bid < NBLK_C) { X = Xa; H = Ha; WN = WNa; SRC = SRCa; DST = DSTa; SS = SSa; }
    else { bid -= NBLK_C; X = Xb; H = Hb; WN = WNb; SRC = SRCb; DST = DSTb; SS = SSb; }

    const int tid = threadIdx.x, lane = tid & 31, wid = tid >> 5;
    const int e0 = bid * 128;
    const uint32_t sHb = smem_u32(sH);
    const uint32_t sBb = smem_u32(sB);

    // stage H tile: 128 rows x 64 halves -> padded stride 72
    {
        const uint4* hg = (const uint4*)(H + (size_t)e0 * 64);
#pragma unroll
        for (int i = 0; i < 4; i++) {
            int idx = tid + 256 * i;            // 1024 x 16B
            int row = idx >> 3, seg = idx & 7;
            uint4 v = hg[idx];
            *(uint4*)((char*)sH + (row * 72 + seg * 8) * 2) = v;
        }
    }

    // x fragments (held in registers for the whole K loop)
    const int row0 = wid * 16 + (lane >> 2);
    const int row1 = row0 + 8;
    const int m2 = (lane & 3) * 2;
    const int eg0 = e0 + row0, eg1 = e0 + row1;
    const int s0 = (eg0 < EE) ? SRC[eg0] : 0;
    const int s1 = (eg1 < EE) ? SRC[eg1] : 0;
    uint32_t xF[4][4];
    {
        const float* x0p = X + (size_t)s0 * 64;
        const float* x1p = X + (size_t)s1 * 64;
#pragma unroll
        for (int ks = 0; ks < 4; ks++) {
            float2 v;
            v = *(const float2*)(x0p + ks * 16 + m2);     xF[ks][0] = f2h2(v.x, v.y);
            v = *(const float2*)(x1p + ks * 16 + m2);     xF[ks][1] = f2h2(v.x, v.y);
            v = *(const float2*)(x0p + ks * 16 + m2 + 8); xF[ks][2] = f2h2(v.x, v.y);
            v = *(const float2*)(x1p + ks * 16 + m2 + 8); xF[ks][3] = f2h2(v.x, v.y);
        }
    }

    float acc[8][4];
#pragma unroll
    for (int j = 0; j < 8; j++)
#pragma unroll
        for (int q = 0; q < 4; q++) acc[j][q] = 0.f;

    // cp.async B-tile issue (64 rows x 128 B = 512 x 16B; 2 per thread)
    const int brow = tid >> 2;            // rows: tid*2/8
    const int bseg0 = (tid & 3) * 2;
#define ISSUE_B(kc, buf) do {                                                     \
        const __half* g0 = WN + brow * KW + (kc) * 64 + bseg0 * 8;                \
        uint32_t sa = sBb + (((buf) * 64 + brow) * 72 + bseg0 * 8) * 2;           \
        asm volatile("cp.async.ca.shared.global [%0], [%1], 16;" :: "r"(sa), "l"(g0)); \
        asm volatile("cp.async.ca.shared.global [%0], [%1], 16;" :: "r"(sa + 16), "l"(g0 + 8)); \
        asm volatile("cp.async.commit_group;");                                   \
    } while (0)

    ISSUE_B(0, 0);

    for (int kc = 0; kc < 65; kc++) {
        const int buf = kc & 1;
        if (kc < 64) {
            ISSUE_B(kc + 1, 1 - buf);
            asm volatile("cp.async.wait_group 1;" ::: "memory");
        } else {
            asm volatile("cp.async.wait_group 0;" ::: "memory");
        }
        __syncthreads();

        uint32_t h2_0, h2_1;
        if (kc < 64) {
            __half hh0 = sH[row0 * 72 + kc];
            __half hh1 = sH[row1 * 72 + kc];
            __half2 p0 = __half2half2(hh0), p1 = __half2half2(hh1);
            h2_0 = *(uint32_t*)&p0; h2_1 = *(uint32_t*)&p1;
        } else {
            __half2 one = __floats2half2_rn(1.f, 1.f);
            h2_0 = *(uint32_t*)&one; h2_1 = h2_0;
        }

#pragma unroll
        for (int ks = 0; ks < 4; ks++) {
            uint32_t bF[8][2];
#pragma unroll
            for (int p = 0; p < 4; p++) {
                int r = p * 16 + (lane & 15);
                int c = ks * 16 + ((lane >> 4) << 3);
                uint32_t addr = sBb + ((buf * 64 + r) * 72 + c) * 2;
                ldsm_x4(bF[2 * p][0], bF[2 * p + 1][0], bF[2 * p][1], bF[2 * p + 1][1], addr);
            }
            uint32_t aR[4];
            aR[0] = hmul2u(xF[ks][0], h2_0);
            aR[1] = hmul2u(xF[ks][1], h2_1);
            aR[2] = hmul2u(xF[ks][2], h2_0);
            aR[3] = hmul2u(xF[ks][3], h2_1);
#pragma unroll
            for (int j = 0; j < 8; j++) mma16816(acc[j], aR, bF[j]);
        }
        __syncthreads();
    }
#undef ISSUE_B

    // epilogue: atomic scatter into SS[dst]
    const int d0 = (eg0 < EE) ? DST[eg0] : -1;
    const int d1 = (eg1 < EE) ? DST[eg1] : -1;
#pragma unroll
    for (int j = 0; j < 8; j++) {
        int c = j * 8 + m2;
        if (d0 >= 0) {
            atomicAdd(&SS[(size_t)d0 * 64 + c],     acc[j][0]);
            atomicAdd(&SS[(size_t)d0 * 64 + c + 1], acc[j][1]);
        }
        if (d1 >= 0) {
            atomicAdd(&SS[(size_t)d1 * 64 + c],     acc[j][2]);
            atomicAdd(&SS[(size_t)d1 * 64 + c + 1], acc[j][3]);
        }
    }
}

// Y[n,:] = relu( SS[n,:]/max(cnt,1) + Xprev[n,:] @ root + bias )  (merged a/b)
__global__ void __launch_bounds__(256) k_finalize2(
    const float* __restrict__ Xb_, const float* __restrict__ SSb_,
    const float* __restrict__ CNTb_, const float* __restrict__ Wab,
    const float* __restrict__ bab, float* __restrict__ Yb_,
    const float* __restrict__ Xa_, const float* __restrict__ SSa_,
    const float* __restrict__ CNTa_, const float* __restrict__ Wba,
    const float* __restrict__ bba, float* __restrict__ Ya_)
{
    __shared__ float sW[64 * 64];
    __shared__ float sB[64];
    __shared__ float sX[64][65];
    int bid = blockIdx.x;
    const float* Xp; const float* SS; const float* CNT; const float* W; const float* b;
    float* Y; int N;
    if (bid < 782) { Xp = Xb_; SS = SSb_; CNT = CNTb_; W = Wab; b = bab; Y = Yb_; N = NB; }
    else { bid -= 782; Xp = Xa_; SS = SSa_; CNT = CNTa_; W = Wba; b = bba; Y = Ya_; N = NA; }
    int tid = threadIdx.x;
    for (int i = tid; i < 4096; i += 256) sW[i] = W[i];
    if (tid < 64) sB[tid] = b[tid];
    int n0 = bid * 64;
    int r = tid >> 2, c0 = (tid & 3) * 16;
    int n = n0 + r;
    if (n < N) {
        const float4* xr = (const float4*)(Xp + (size_t)n * 64 + c0);
#pragma unroll
        for (int k = 0; k < 4; k++) {
            float4 v = xr[k];
            sX[r][c0 + 4 * k + 0] = v.x; sX[r][c0 + 4 * k + 1] = v.y;
            sX[r][c0 + 4 * k + 2] = v.z; sX[r][c0 + 4 * k + 3] = v.w;
        }
    } else {
#pragma unroll
        for (int k = 0; k < 16; k++) sX[r][c0 + k] = 0.f;
    }
    __syncthreads();
    int o0 = (tid & 3) * 16;
    float acc[16];
#pragma unroll
    for (int j = 0; j < 16; j++) acc[j] = sB[o0 + j];
#pragma unroll 8
    for (int d = 0; d < 64; d++) {
        float xv = sX[r][d];
#pragma unroll
        for (int j = 0; j < 16; j++) acc[j] += xv * sW[d * 64 + o0 + j];
    }
    if (n < N) {
        float ic = 1.f / fmaxf(CNT[n], 1.f);
#pragma unroll
        for (int j = 0; j < 16; j++) {
            float v = acc[j] + SS[(size_t)n * 64 + o0 + j] * ic;
            Y[(size_t)n * 64 + o0 + j] = fmaxf(v, 0.f);
        }
    }
}

// ---------------- launcher ----------------
static void* sym(const void* s) {
    void* p = nullptr;
    cudaGetSymbolAddress(&p, s);
    return p;
}

extern "C" void kernel_launch(void* const* d_in, const int* in_sizes, int n_in,
                              void* d_out, int out_size)
{
    const int*   x_a      = (const int*)d_in[0];
    const int*   x_b      = (const int*)d_in[1];
    const int*   ei_ab    = (const int*)d_in[2];   // [2,E]
    const int*   ei_ba    = (const int*)d_in[3];
    const float* ea_ab    = (const float*)d_in[4];
    const float* ea_ba    = (const float*)d_in[5];
    const float* emb_a    = (const float*)d_in[6];
    const float* emb_b    = (const float*)d_in[7];
    const float* Wn_a     = (const float*)d_in[8];
    const float* bn_a     = (const float*)d_in[9];
    const float* Wn_b     = (const float*)d_in[10];
    const float* bn_b     = (const float*)d_in[11];
    const float* W1_ab    = (const float*)d_in[12];
    const float* b1_ab    = (const float*)d_in[13];
    const float* W2_ab    = (const float*)d_in[14];
    const float* b2_ab    = (const float*)d_in[15];
    const float* W1_ba    = (const float*)d_in[16];
    const float* b1_ba    = (const float*)d_in[17];
    const float* W2_ba    = (const float*)d_in[18];
    const float* b2_ba    = (const float*)d_in[19];
    const float* root0_ab = (const float*)d_in[20];
    const float* bias0_ab = (const float*)d_in[21];
    const float* root0_ba = (const float*)d_in[22];
    const float* bias0_ba = (const float*)d_in[23];
    const float* root1_ab = (const float*)d_in[24];
    const float* bias1_ab = (const float*)d_in[25];
    const float* root1_ba = (const float*)d_in[26];
    const float* bias1_ba = (const float*)d_in[27];

    float*  xa0 = (float*)sym(g_xa0);
    float*  xb0 = (float*)sym(g_xb0);
    float*  xa1 = (float*)sym(g_xa1);
    float*  xb1 = (float*)sym(g_xb1);
    __half* hab = (__half*)sym(g_hab);
    __half* hba = (__half*)sym(g_hba);
    __half* wnab = (__half*)sym(g_wn_ab);
    __half* wnba = (__half*)sym(g_wn_ba);
    float*  ss  = (float*)sym(g_ss);
    float*  cnt = (float*)sym(g_cnt);
    float*  ssa = ss;
    float*  ssb = ss + (size_t)NA * DD;
    float*  cnta = cnt;
    float*  cntb = cnt + NA;

    const int* src_ab = ei_ab;
    const int* dst_ab = ei_ab + EE;
    const int* src_ba = ei_ba;
    const int* dst_ba = ei_ba + EE;

    float* out = (float*)d_out;

    // counts (layer-invariant)
    k_zero<<<(NA + NB + 255) / 256, 256>>>(cnt, NA + NB);
    k_count2<<<(2 * EE + 255) / 256, 256>>>(dst_ab, dst_ba, cnta, cntb);

    // initial node features (merged a+b)
    k_node_linear2<<<1564, 256>>>(emb_a, x_a, Wn_a, bn_a, xa0,
                                  emb_b, x_b, Wn_b, bn_b, xb0);

    // edge MLP hidden (merged, fp16, zero-padded)
    k_edge_mlp2<<<940, 256>>>(ea_ab, W1_ab, b1_ab, hab,
                              ea_ba, W1_ba, b1_ba, hba);

    // pack W2+b2 (merged)
    k_pack2<<<(2 * 64 * KW + 255) / 256, 256>>>(W2_ab, b2_ab, wnab,
                                                W2_ba, b2_ba, wnba);

    // ---- layer 0 ----
    k_zero<<<((NA + NB) * DD + 255) / 256, 256>>>(ss, (NA + NB) * DD);
    k_conv2<<<2 * NBLK_C, 256>>>(xa0, hab, wnab, src_ab, dst_ab, ssb,
                                 xb0, hba, wnba, src_ba, dst_ba, ssa);
    k_finalize2<<<1564, 256>>>(xb0, ssb, cntb, root0_ab, bias0_ab, xb1,
                               xa0, ssa, cnta, root0_ba, bias0_ba, xa1);

    // ---- layer 1 ----
    k_zero<<<((NA + NB) * DD + 255) / 256, 256>>>(ss, (NA + NB) * DD);
    k_conv2<<<2 * NBLK_C, 256>>>(xa1, hab, wnab, src_ab, dst_ab, ssb,
                                 xb1, hba, wnba, src_ba, dst_ba, ssa);
    k_finalize2<<<1564, 256>>>(xb1, ssb, cntb, root1_ab, bias1_ab, out + (size_t)NA * DD,
                               xa1, ssa, cnta, root1_ba, bias1_ba, out);
}